// round 14
// baseline (speedup 1.0000x reference)
#include <cuda_runtime.h>
#include <cstdint>

#define B_    16
#define C_    256
#define HW_   3136
#define Wim_  56
#define CI_   32
#define CG_   64
#define NP_   784
#define WP_   28
#define CCAT_ 128
#define NFLAT_ (B_ * HW_)        // 50176
#define NTILE_ (NFLAT_ / 128)    // 392
#define HWB_   13
#define NBLK2_ (HWB_ * B_)       // 208
#define NCHK_  14                // S chunks
#define CHW_   56                // positions per S chunk

typedef unsigned long long u64;

#define FMA2(d, a, b) asm("fma.rn.f32x2 %0, %1, %2, %0;" : "+l"(d) : "l"(a), "l"(b))
#define DUP2(d, s)    asm("mov.b64 %0, {%1, %1};" : "=l"(d) : "f"(s))
#define SWZ(o) ((o) ^ ((((o) >> 5) & 1) << 2))

__device__ __forceinline__ unsigned enc_key(float f) {
    unsigned b = __float_as_uint(f);
    return (b & 0x80000000u) ? ~b : (b | 0x80000000u);
}
__device__ __forceinline__ float dec_key(unsigned u) {
    unsigned b = (u & 0x80000000u) ? (u & 0x7fffffffu) : ~u;
    return __uint_as_float(b);
}

// ---------------- scratch ----------------
__device__ float d_wcatT[C_ * CCAT_];
__device__ float d_wzT[CG_ * C_];
__device__ float d_bcat[CCAT_];
__device__ float d_ps1[C_ * B_], d_pq1[C_ * B_];
__device__ float d_ps2[CG_ * NBLK2_], d_pq2[CG_ * NBLK2_];
__device__ float d_a2[CG_], d_b2[CG_];
__device__ float d_theta[B_ * CI_ * HW_];
__device__ unsigned d_gx_u[B_ * CG_ * NP_];
__device__ unsigned d_phix_u[B_ * CI_ * NP_];
__device__ float d_Sp[B_ * NCHK_ * CI_ * CG_];
__device__ float d_y[B_ * CG_ * HW_];

// ---------------- front: BN1 partials + weight transposes + pool init ----------------
__global__ void __launch_bounds__(256) k_front(
    const float* __restrict__ x,
    const float* __restrict__ w_g, const float* __restrict__ b_g,
    const float* __restrict__ w_t, const float* __restrict__ b_t,
    const float* __restrict__ w_p, const float* __restrict__ b_p,
    const float* __restrict__ wz)
{
    const int c = blockIdx.x;
    const int b = blockIdx.y;
    const int tid = threadIdx.x;

    if (b == 1 && c < CCAT_) {
        int row = c, k = tid;
        float v;
        if (row < 64)       v = w_g[row * C_ + k];
        else if (row < 96)  v = w_t[(row - 64) * C_ + k];
        else                v = w_p[(row - 96) * C_ + k];
        d_wcatT[k * CCAT_ + row] = v;
        if (tid == 0)
            d_bcat[row] = (row < 64) ? b_g[row] : (row < 96 ? b_t[row - 64] : b_p[row - 96]);
    }
    if (b == 2 && c < CG_) {
        d_wzT[c * C_ + tid] = wz[tid * CG_ + c];
    }
    {
        int gid = (b * 256 + c) * 256 + tid;
        const int tot_g = B_ * CG_ * NP_;
        const int tot_p = B_ * CI_ * NP_;
        for (int i = gid; i < tot_g; i += 4096 * 256) d_gx_u[i] = 0x007fffffu;
        for (int i = gid; i < tot_p; i += 4096 * 256) d_phix_u[i] = 0x007fffffu;
    }

    const float4* p = (const float4*)(x + ((size_t)(b * C_ + c)) * HW_);
    float s = 0.f, q = 0.f;
    for (int i = tid; i < HW_ / 4; i += 256) {
        float4 v = p[i];
        s += v.x + v.y + v.z + v.w;
        q += v.x * v.x + v.y * v.y + v.z * v.z + v.w * v.w;
    }
    __shared__ float ss[8], sq[8];
    for (int o = 16; o > 0; o >>= 1) {
        s += __shfl_down_sync(0xffffffffu, s, o);
        q += __shfl_down_sync(0xffffffffu, q, o);
    }
    int lane = tid & 31, wid = tid >> 5;
    if (lane == 0) { ss[wid] = s; sq[wid] = q; }
    __syncthreads();
    if (tid == 0) {
        float S = 0.f, Q = 0.f;
        for (int w = 0; w < 8; w++) { S += ss[w]; Q += sq[w]; }
        d_ps1[c * B_ + b] = S;
        d_pq1[c * B_ + b] = Q;
    }
}

// ---------------- conv_cat (R13-proven): conflict-free staging + swizzled B ----------------
__global__ void __launch_bounds__(256, 2) k_conv_cat(const float* __restrict__ x,
                                                     const float* __restrict__ gamma,
                                                     const float* __restrict__ beta) {
    const int tid = threadIdx.x;
    const int tx = tid & 15, ty = tid >> 4;
    const int n0 = blockIdx.x * 128;

    __shared__ float As[2][16][128];
    __shared__ float Bs[2][16][132];
    __shared__ float sa1[C_], sb1[C_];

    {
        float s = 0.f, q = 0.f;
#pragma unroll
        for (int b = 0; b < B_; b++) { s += d_ps1[tid * B_ + b]; q += d_pq1[tid * B_ + b]; }
        const float invN = 1.f / (float)(B_ * HW_);
        float mean = s * invN;
        float var = q * invN - mean * mean;
        float inv = rsqrtf(var + 1e-5f);
        float g = gamma[tid];
        sa1[tid] = g * inv;
        sb1[tid] = beta[tid] - mean * g * inv;
    }

    u64 acc2[4][8];
#pragma unroll
    for (int i = 0; i < 4; i++)
#pragma unroll
        for (int j = 0; j < 8; j++) acc2[i][j] = 0ull;

    int kkA[2], m4A[2];
#pragma unroll
    for (int i = 0; i < 2; i++) {
        int idx = tid + i * 256;
        kkA[i] = idx >> 5;
        m4A[i] = (idx & 31) << 2;
    }
    int kB[2], n4Bs[2], ptrB[2];
#pragma unroll
    for (int i = 0; i < 2; i++) {
        int idx = tid + i * 256;
        kB[i] = idx >> 5;
        int n4 = (idx & 31) << 2;
        n4Bs[i] = SWZ(n4);
        int nf = n0 + n4;
        int bb = nf / HW_;
        ptrB[i] = (bb * C_ + kB[i]) * HW_ + (nf - bb * HW_);
    }
    const int oB1 = SWZ(tx * 8), oB2 = SWZ(tx * 8 + 4);

    float4 ra[2], rb[2];
#pragma unroll
    for (int i = 0; i < 2; i++) {
        ra[i] = *(const float4*)(d_wcatT + kkA[i] * CCAT_ + m4A[i]);
        rb[i] = *(const float4*)(x + ptrB[i]);
    }
    __syncthreads();

#pragma unroll 1
    for (int kt = 0; kt < 16; kt++) {
        const int cur = kt & 1;
#pragma unroll
        for (int i = 0; i < 2; i++)
            *(float4*)(&As[cur][kkA[i]][m4A[i]]) = ra[i];
#pragma unroll
        for (int i = 0; i < 2; i++) {
            int c = kt * 16 + kB[i];
            float a = sa1[c], bb = sb1[c];
            float4 v = rb[i];
            v.x = fmaxf(fmaf(a, v.x, bb), 0.f);
            v.y = fmaxf(fmaf(a, v.y, bb), 0.f);
            v.z = fmaxf(fmaf(a, v.z, bb), 0.f);
            v.w = fmaxf(fmaf(a, v.w, bb), 0.f);
            *(float4*)(&Bs[cur][kB[i]][n4Bs[i]]) = v;
        }
        __syncthreads();
        if (kt < 15) {
            int k0n = (kt + 1) * 16;
#pragma unroll
            for (int i = 0; i < 2; i++) {
                ra[i] = *(const float4*)(d_wcatT + (k0n + kkA[i]) * CCAT_ + m4A[i]);
                rb[i] = *(const float4*)(x + ptrB[i] + k0n * HW_);
            }
        }
#pragma unroll
        for (int k = 0; k < 16; k++) {
            ulonglong2 pa0 = *(const ulonglong2*)(&As[cur][k][ty * 8]);
            ulonglong2 pa1 = *((const ulonglong2*)(&As[cur][k][ty * 8]) + 1);
            u64 av2[4] = {pa0.x, pa0.y, pa1.x, pa1.y};
            float4 bq0 = *(const float4*)(&Bs[cur][k][oB1]);
            float4 bq1 = *(const float4*)(&Bs[cur][k][oB2]);
            u64 bd[8];
            DUP2(bd[0], bq0.x); DUP2(bd[1], bq0.y); DUP2(bd[2], bq0.z); DUP2(bd[3], bq0.w);
            DUP2(bd[4], bq1.x); DUP2(bd[5], bq1.y); DUP2(bd[6], bq1.z); DUP2(bd[7], bq1.w);
#pragma unroll
            for (int j = 0; j < 8; j++)
#pragma unroll
                for (int i2 = 0; i2 < 4; i2++)
                    FMA2(acc2[i2][j], av2[i2], bd[j]);
        }
    }

#pragma unroll
    for (int i2 = 0; i2 < 4; i2++) {
#pragma unroll
        for (int half = 0; half < 2; half++) {
            int ch = ty * 8 + i2 * 2 + half;
            float r[8];
#pragma unroll
            for (int j = 0; j < 8; j++) {
                float2 p = *(const float2*)(&acc2[i2][j]);
                r[j] = half ? p.y : p.x;
            }
            if (ch >= 64 && ch < 96) {
                float bias = d_bcat[ch];
#pragma unroll
                for (int q = 0; q < 8; q += 4) {
                    int nf = n0 + tx * 8 + q;
                    int bb = nf / HW_;
                    int hw = nf - bb * HW_;
                    float4 v = make_float4(r[q] + bias, r[q + 1] + bias,
                                           r[q + 2] + bias, r[q + 3] + bias);
                    *(float4*)(d_theta + ((size_t)(bb * CI_ + (ch - 64))) * HW_ + hw) = v;
                }
            } else {
                unsigned* arr = (ch < 64) ? d_gx_u : d_phix_u;
                int pc = (ch < 64) ? ch : (ch - 96);
                int pst = (ch < 64) ? CG_ : CI_;
#pragma unroll
                for (int p = 0; p < 4; p++) {
                    float v = fmaxf(r[2 * p], r[2 * p + 1]);
                    int nf = n0 + tx * 8 + 2 * p;
                    int bb = nf / HW_;
                    int hw = nf - bb * HW_;
                    int h = hw / Wim_, w = hw - h * Wim_;
                    int pi = (h >> 1) * WP_ + (w >> 1);
                    atomicMax(arr + (bb * pst + pc) * NP_ + pi, enc_key(v));
                }
            }
        }
    }
}

// ---------------- S partials: 14 chunks of 56 positions ----------------
__global__ void __launch_bounds__(256) k_S_part() {
    const int b = blockIdx.x;
    const int ch = blockIdx.y;
    const int m0 = ch * CHW_;
    __shared__ float phs[CI_][60];
    __shared__ float gs[CG_][60];
    float acc[8];
#pragma unroll
    for (int r = 0; r < 8; r++) acc[r] = 0.f;
    const int tid = threadIdx.x;
    const int ii = tid >> 3;
    const int cg_lane = tid & 7;

    for (int i = tid; i < CI_ * CHW_; i += 256) {
        int r = i / CHW_, mm = i % CHW_;
        unsigned u = d_phix_u[(b * CI_ + r) * NP_ + m0 + mm];
        phs[r][mm] = dec_key(u) + d_bcat[96 + r];
    }
    for (int i = tid; i < CG_ * CHW_; i += 256) {
        int r = i / CHW_, mm = i % CHW_;
        unsigned u = d_gx_u[(b * CG_ + r) * NP_ + m0 + mm];
        gs[r][mm] = dec_key(u) + d_bcat[r];
    }
    __syncthreads();
    for (int mm4 = 0; mm4 < CHW_; mm4 += 4) {
        float4 pv = *(const float4*)(&phs[ii][mm4]);
#pragma unroll
        for (int j = 0; j < 8; j++) {
            float4 gv = *(const float4*)(&gs[cg_lane + 8 * j][mm4]);
            acc[j] = fmaf(pv.x, gv.x, acc[j]);
            acc[j] = fmaf(pv.y, gv.y, acc[j]);
            acc[j] = fmaf(pv.z, gv.z, acc[j]);
            acc[j] = fmaf(pv.w, gv.w, acc[j]);
        }
    }
#pragma unroll
    for (int j = 0; j < 8; j++)
        d_Sp[((b * NCHK_ + ch) * CI_ + ii) * CG_ + cg_lane + 8 * j] = acc[j];
}

// ---------------- y = S^T @ theta, cg quarter per block (16 channels) + fused BN2 partials ----------------
__global__ void __launch_bounds__(256) k_y() {
    const int b = blockIdx.y;
    const int z = blockIdx.z;               // quarter: channels [16z, 16z+16)
    const int tid = threadIdx.x;
    const int hw = blockIdx.x * 256 + tid;
    const bool valid = hw < HW_;

    __shared__ float Sh[CI_][16];
    __shared__ float sbuf[256][17];
    __shared__ float psS[8][16], psQ[8][16];

    for (int idx = tid; idx < CI_ * 16; idx += 256) {
        int i = idx >> 4, cl = idx & 15;
        float s = 0.f;
#pragma unroll
        for (int ch = 0; ch < NCHK_; ch++)
            s += d_Sp[((b * NCHK_ + ch) * CI_ + i) * CG_ + 16 * z + cl];
        Sh[i][cl] = s * (1.f / (float)NP_);
    }
    __syncthreads();

    u64 acc2[8];
#pragma unroll
    for (int c2 = 0; c2 < 8; c2++) acc2[c2] = 0ull;

    if (valid) {
#pragma unroll 4
        for (int i = 0; i < CI_; i++) {
            float t = d_theta[((size_t)(b * CI_ + i)) * HW_ + hw];
            u64 td; DUP2(td, t);
            const u64* row = (const u64*)(&Sh[i][0]);
#pragma unroll
            for (int c2 = 0; c2 < 8; c2++)
                FMA2(acc2[c2], td, row[c2]);
        }
    }

#pragma unroll
    for (int c2 = 0; c2 < 8; c2++) {
        float2 p = *(const float2*)(&acc2[c2]);
        if (valid) {
            d_y[((size_t)(b * CG_ + 16 * z + 2 * c2)) * HW_ + hw] = p.x;
            d_y[((size_t)(b * CG_ + 16 * z + 2 * c2 + 1)) * HW_ + hw] = p.y;
        }
        sbuf[tid][2 * c2] = valid ? p.x : 0.f;
        sbuf[tid][2 * c2 + 1] = valid ? p.y : 0.f;
    }
    __syncthreads();

    // per-block channel sums: 8 segments x 16 channels (threads 0..127)
    if (tid < 128) {
        int cl = tid & 15, seg = tid >> 4;
        float s = 0.f, q = 0.f;
#pragma unroll
        for (int r = 0; r < 32; r++) {
            float v = sbuf[seg * 32 + r][cl];
            s += v;
            q += v * v;
        }
        psS[seg][cl] = s;
        psQ[seg][cl] = q;
    }
    __syncthreads();
    if (tid < 16) {
        float S = 0.f, Q = 0.f;
#pragma unroll
        for (int seg = 0; seg < 8; seg++) { S += psS[seg][tid]; Q += psQ[seg][tid]; }
        int blk = blockIdx.x + HWB_ * b;
        d_ps2[(16 * z + tid) * NBLK2_ + blk] = S;
        d_pq2[(16 * z + tid) * NBLK2_ + blk] = Q;
    }
}

// ---------------- BN2 finalize ----------------
__global__ void __launch_bounds__(256) k_bn2_final(const float* __restrict__ gamma2,
                                                   const float* __restrict__ beta2) {
    const int tid = threadIdx.x;
    const int ch = tid & 63, qr = tid >> 6;
    float s = 0.f, q = 0.f;
    for (int p = qr * 52; p < (qr + 1) * 52; p++) {
        s += d_ps2[ch * NBLK2_ + p];
        q += d_pq2[ch * NBLK2_ + p];
    }
    __shared__ float ssm[4][64], sqm[4][64];
    ssm[qr][ch] = s;
    sqm[qr][ch] = q;
    __syncthreads();
    if (tid < 64) {
        float S = ssm[0][tid] + ssm[1][tid] + ssm[2][tid] + ssm[3][tid];
        float Q = sqm[0][tid] + sqm[1][tid] + sqm[2][tid] + sqm[3][tid];
        const float invN = 1.f / (float)(B_ * HW_);
        float mean = S * invN;
        float var = Q * invN - mean * mean;
        float inv = rsqrtf(var + 1e-5f);
        float g = gamma2[tid];
        d_a2[tid] = g * inv;
        d_b2[tid] = beta2[tid] - mean * g * inv;
    }
}

// ---------------- final GEMM (R13-proven): single K-pass, conflict-free ----------------
__global__ void __launch_bounds__(256) k_final(const float* __restrict__ bz,
                                               const float* __restrict__ x,
                                               float* __restrict__ out) {
    extern __shared__ float smemf[];
    float* As = smemf;
    float* Bs = smemf + 64 * 128;
    __shared__ float sa2[CG_], sb2[CG_];

    const int b  = blockIdx.z;
    const int m0 = blockIdx.y * 128;
    const int n0 = blockIdx.x * 128;
    const int tid = threadIdx.x;
    const int tx = tid & 15, ty = tid >> 4;

    if (tid < CG_) { sa2[tid] = d_a2[tid]; sb2[tid] = d_b2[tid]; }
    __syncthreads();

#pragma unroll
    for (int i = 0; i < 8; i++) {
        int idx = tid + i * 256;
        int k = idx >> 5;
        int m4 = (idx & 31) << 2;
        float4 v = *(const float4*)(d_wzT + k * C_ + m0 + m4);
        *(float4*)(&As[k * 128 + m4]) = v;
    }
#pragma unroll
    for (int i = 0; i < 8; i++) {
        int idx = tid + i * 256;
        int k = idx >> 5;
        int n4 = (idx & 31) << 2;
        int hw = n0 + n4;
        float4 v = make_float4(0.f, 0.f, 0.f, 0.f);
        if (hw < HW_)
            v = *(const float4*)(d_y + ((size_t)(b * CG_ + k)) * HW_ + hw);
        float a = sa2[k], bb = sb2[k];
        v.x = fmaxf(fmaf(a, v.x, bb), 0.f);
        v.y = fmaxf(fmaf(a, v.y, bb), 0.f);
        v.z = fmaxf(fmaf(a, v.z, bb), 0.f);
        v.w = fmaxf(fmaf(a, v.w, bb), 0.f);
        *(float4*)(&Bs[k * 132 + SWZ(n4)]) = v;
    }
    __syncthreads();

    const int oB1 = SWZ(tx * 8), oB2 = SWZ(tx * 8 + 4);
    u64 acc2[4][8];
#pragma unroll
    for (int i = 0; i < 4; i++)
#pragma unroll
        for (int j = 0; j < 8; j++) acc2[i][j] = 0ull;

#pragma unroll 4
    for (int k = 0; k < 64; k++) {
        ulonglong2 pa0 = *(const ulonglong2*)(&As[k * 128 + ty * 8]);
        ulonglong2 pa1 = *((const ulonglong2*)(&As[k * 128 + ty * 8]) + 1);
        u64 av2[4] = {pa0.x, pa0.y, pa1.x, pa1.y};
        float4 bq0 = *(const float4*)(&Bs[k * 132 + oB1]);
        float4 bq1 = *(const float4*)(&Bs[k * 132 + oB2]);
        u64 bd[8];
        DUP2(bd[0], bq0.x); DUP2(bd[1], bq0.y); DUP2(bd[2], bq0.z); DUP2(bd[3], bq0.w);
        DUP2(bd[4], bq1.x); DUP2(bd[5], bq1.y); DUP2(bd[6], bq1.z); DUP2(bd[7], bq1.w);
#pragma unroll
        for (int j = 0; j < 8; j++)
#pragma unroll
            for (int i2 = 0; i2 < 4; i2++)
                FMA2(acc2[i2][j], av2[i2], bd[j]);
    }

#pragma unroll
    for (int i2 = 0; i2 < 4; i2++) {
#pragma unroll
        for (int half = 0; half < 2; half++) {
            int m = m0 + ty * 8 + i2 * 2 + half;
            float bias = bz[m];
            float r[8];
#pragma unroll
            for (int j = 0; j < 8; j++) {
                float2 p = *(const float2*)(&acc2[i2][j]);
                r[j] = (half == 0 ? p.x : p.y) + bias;
            }
#pragma unroll
            for (int j4 = 0; j4 < 8; j4 += 4) {
                int n = n0 + tx * 8 + j4;
                if (n < HW_) {
                    size_t off = ((size_t)(b * C_ + m)) * HW_ + n;
                    float4 xi = *(const float4*)(x + off);
                    float4 v = make_float4(r[j4] + xi.x, r[j4 + 1] + xi.y,
                                           r[j4 + 2] + xi.z, r[j4 + 3] + xi.w);
                    *(float4*)(out + off) = v;
                }
            }
        }
    }
}

#define SMEM_FINAL ((64 * 128 + 64 * 132) * 4)

// ---------------- launch ----------------
extern "C" void kernel_launch(void* const* d_in, const int* in_sizes, int n_in,
                              void* d_out, int out_size) {
    const float* x   = (const float*)d_in[0];
    const float* g1  = (const float*)d_in[1];
    const float* be1 = (const float*)d_in[2];
    const float* w_g = (const float*)d_in[3];
    const float* b_g = (const float*)d_in[4];
    const float* w_t = (const float*)d_in[5];
    const float* b_t = (const float*)d_in[6];
    const float* w_p = (const float*)d_in[7];
    const float* b_p = (const float*)d_in[8];
    const float* g2  = (const float*)d_in[9];
    const float* be2 = (const float*)d_in[10];
    const float* wz  = (const float*)d_in[11];
    const float* bz  = (const float*)d_in[12];
    float* out = (float*)d_out;

    static int smem_set = 0;
    if (!smem_set) {
        cudaFuncSetAttribute(k_final, cudaFuncAttributeMaxDynamicSharedMemorySize, SMEM_FINAL);
        smem_set = 1;
    }

    k_front<<<dim3(C_, B_), 256>>>(x, w_g, b_g, w_t, b_t, w_p, b_p, wz);
    k_conv_cat<<<NTILE_, 256>>>(x, g1, be1);
    k_S_part<<<dim3(B_, NCHK_), 256>>>();
    k_y<<<dim3(HWB_, B_, 4), 256>>>();
    k_bn2_final<<<1, 256>>>(g2, be2);
    k_final<<<dim3(25, 2, B_), 256, SMEM_FINAL>>>(bz, x, out);
}

// round 15
// speedup vs baseline: 1.0135x; 1.0135x over previous
#include <cuda_runtime.h>
#include <cstdint>

#define B_    16
#define C_    256
#define HW_   3136
#define Wim_  56
#define CI_   32
#define CG_   64
#define NP_   784
#define WP_   28
#define CCAT_ 128
#define NFLAT_ (B_ * HW_)        // 50176
#define NTILE_ (NFLAT_ / 128)    // 392
#define HWB_   13
#define NBLK2_ (HWB_ * B_)       // 208
#define NCHK_  14                // S chunks
#define CHW_   56                // positions per S chunk

typedef unsigned long long u64;

#define FMA2(d, a, b) asm("fma.rn.f32x2 %0, %1, %2, %0;" : "+l"(d) : "l"(a), "l"(b))
#define DUP2(d, s)    asm("mov.b64 %0, {%1, %1};" : "=l"(d) : "f"(s))
#define SWZ(o) ((o) ^ ((((o) >> 5) & 1) << 2))

__device__ __forceinline__ unsigned enc_key(float f) {
    unsigned b = __float_as_uint(f);
    return (b & 0x80000000u) ? ~b : (b | 0x80000000u);
}
__device__ __forceinline__ float dec_key(unsigned u) {
    unsigned b = (u & 0x80000000u) ? (u & 0x7fffffffu) : ~u;
    return __uint_as_float(b);
}

// ---------------- scratch ----------------
__device__ float d_wcatT[C_ * CCAT_];
__device__ float d_wzT[CG_ * C_];
__device__ float d_bcat[CCAT_];
__device__ float d_ps1[C_ * B_], d_pq1[C_ * B_];
__device__ float d_ps2[CG_ * NBLK2_], d_pq2[CG_ * NBLK2_];
__device__ float d_a2[CG_], d_b2[CG_];
__device__ float d_theta[B_ * CI_ * HW_];
__device__ unsigned d_gx_u[B_ * CG_ * NP_];
__device__ unsigned d_phix_u[B_ * CI_ * NP_];
__device__ float d_Sp[B_ * NCHK_ * CI_ * CG_];
__device__ float d_y[B_ * CG_ * HW_];

// ---------------- front: BN1 partials + weight transposes + pool init ----------------
__global__ void __launch_bounds__(256) k_front(
    const float* __restrict__ x,
    const float* __restrict__ w_g, const float* __restrict__ b_g,
    const float* __restrict__ w_t, const float* __restrict__ b_t,
    const float* __restrict__ w_p, const float* __restrict__ b_p,
    const float* __restrict__ wz)
{
    const int c = blockIdx.x;
    const int b = blockIdx.y;
    const int tid = threadIdx.x;

    if (b == 1 && c < CCAT_) {
        int row = c, k = tid;
        float v;
        if (row < 64)       v = w_g[row * C_ + k];
        else if (row < 96)  v = w_t[(row - 64) * C_ + k];
        else                v = w_p[(row - 96) * C_ + k];
        d_wcatT[k * CCAT_ + row] = v;
        if (tid == 0)
            d_bcat[row] = (row < 64) ? b_g[row] : (row < 96 ? b_t[row - 64] : b_p[row - 96]);
    }
    if (b == 2 && c < CG_) {
        d_wzT[c * C_ + tid] = wz[tid * CG_ + c];
    }
    {
        int gid = (b * 256 + c) * 256 + tid;
        const int tot_g = B_ * CG_ * NP_;
        const int tot_p = B_ * CI_ * NP_;
        for (int i = gid; i < tot_g; i += 4096 * 256) d_gx_u[i] = 0x007fffffu;
        for (int i = gid; i < tot_p; i += 4096 * 256) d_phix_u[i] = 0x007fffffu;
    }

    const float4* p = (const float4*)(x + ((size_t)(b * C_ + c)) * HW_);
    float s = 0.f, q = 0.f;
    for (int i = tid; i < HW_ / 4; i += 256) {
        float4 v = p[i];
        s += v.x + v.y + v.z + v.w;
        q += v.x * v.x + v.y * v.y + v.z * v.z + v.w * v.w;
    }
    __shared__ float ss[8], sq[8];
    for (int o = 16; o > 0; o >>= 1) {
        s += __shfl_down_sync(0xffffffffu, s, o);
        q += __shfl_down_sync(0xffffffffu, q, o);
    }
    int lane = tid & 31, wid = tid >> 5;
    if (lane == 0) { ss[wid] = s; sq[wid] = q; }
    __syncthreads();
    if (tid == 0) {
        float S = 0.f, Q = 0.f;
        for (int w = 0; w < 8; w++) { S += ss[w]; Q += sq[w]; }
        d_ps1[c * B_ + b] = S;
        d_pq1[c * B_ + b] = Q;
    }
}

// ---------------- conv_cat (R13-proven): conflict-free staging + swizzled B ----------------
__global__ void __launch_bounds__(256, 2) k_conv_cat(const float* __restrict__ x,
                                                     const float* __restrict__ gamma,
                                                     const float* __restrict__ beta) {
    const int tid = threadIdx.x;
    const int tx = tid & 15, ty = tid >> 4;
    const int n0 = blockIdx.x * 128;

    __shared__ float As[2][16][128];
    __shared__ float Bs[2][16][132];
    __shared__ float sa1[C_], sb1[C_];

    {
        float s = 0.f, q = 0.f;
#pragma unroll
        for (int b = 0; b < B_; b++) { s += d_ps1[tid * B_ + b]; q += d_pq1[tid * B_ + b]; }
        const float invN = 1.f / (float)(B_ * HW_);
        float mean = s * invN;
        float var = q * invN - mean * mean;
        float inv = rsqrtf(var + 1e-5f);
        float g = gamma[tid];
        sa1[tid] = g * inv;
        sb1[tid] = beta[tid] - mean * g * inv;
    }

    u64 acc2[4][8];
#pragma unroll
    for (int i = 0; i < 4; i++)
#pragma unroll
        for (int j = 0; j < 8; j++) acc2[i][j] = 0ull;

    int kkA[2], m4A[2];
#pragma unroll
    for (int i = 0; i < 2; i++) {
        int idx = tid + i * 256;
        kkA[i] = idx >> 5;
        m4A[i] = (idx & 31) << 2;
    }
    int kB[2], n4Bs[2], ptrB[2];
#pragma unroll
    for (int i = 0; i < 2; i++) {
        int idx = tid + i * 256;
        kB[i] = idx >> 5;
        int n4 = (idx & 31) << 2;
        n4Bs[i] = SWZ(n4);
        int nf = n0 + n4;
        int bb = nf / HW_;
        ptrB[i] = (bb * C_ + kB[i]) * HW_ + (nf - bb * HW_);
    }
    const int oB1 = SWZ(tx * 8), oB2 = SWZ(tx * 8 + 4);

    float4 ra[2], rb[2];
#pragma unroll
    for (int i = 0; i < 2; i++) {
        ra[i] = *(const float4*)(d_wcatT + kkA[i] * CCAT_ + m4A[i]);
        rb[i] = *(const float4*)(x + ptrB[i]);
    }
    __syncthreads();

#pragma unroll 1
    for (int kt = 0; kt < 16; kt++) {
        const int cur = kt & 1;
#pragma unroll
        for (int i = 0; i < 2; i++)
            *(float4*)(&As[cur][kkA[i]][m4A[i]]) = ra[i];
#pragma unroll
        for (int i = 0; i < 2; i++) {
            int c = kt * 16 + kB[i];
            float a = sa1[c], bb = sb1[c];
            float4 v = rb[i];
            v.x = fmaxf(fmaf(a, v.x, bb), 0.f);
            v.y = fmaxf(fmaf(a, v.y, bb), 0.f);
            v.z = fmaxf(fmaf(a, v.z, bb), 0.f);
            v.w = fmaxf(fmaf(a, v.w, bb), 0.f);
            *(float4*)(&Bs[cur][kB[i]][n4Bs[i]]) = v;
        }
        __syncthreads();
        if (kt < 15) {
            int k0n = (kt + 1) * 16;
#pragma unroll
            for (int i = 0; i < 2; i++) {
                ra[i] = *(const float4*)(d_wcatT + (k0n + kkA[i]) * CCAT_ + m4A[i]);
                rb[i] = *(const float4*)(x + ptrB[i] + k0n * HW_);
            }
        }
#pragma unroll
        for (int k = 0; k < 16; k++) {
            ulonglong2 pa0 = *(const ulonglong2*)(&As[cur][k][ty * 8]);
            ulonglong2 pa1 = *((const ulonglong2*)(&As[cur][k][ty * 8]) + 1);
            u64 av2[4] = {pa0.x, pa0.y, pa1.x, pa1.y};
            float4 bq0 = *(const float4*)(&Bs[cur][k][oB1]);
            float4 bq1 = *(const float4*)(&Bs[cur][k][oB2]);
            u64 bd[8];
            DUP2(bd[0], bq0.x); DUP2(bd[1], bq0.y); DUP2(bd[2], bq0.z); DUP2(bd[3], bq0.w);
            DUP2(bd[4], bq1.x); DUP2(bd[5], bq1.y); DUP2(bd[6], bq1.z); DUP2(bd[7], bq1.w);
#pragma unroll
            for (int j = 0; j < 8; j++)
#pragma unroll
                for (int i2 = 0; i2 < 4; i2++)
                    FMA2(acc2[i2][j], av2[i2], bd[j]);
        }
    }

#pragma unroll
    for (int i2 = 0; i2 < 4; i2++) {
#pragma unroll
        for (int half = 0; half < 2; half++) {
            int ch = ty * 8 + i2 * 2 + half;
            float r[8];
#pragma unroll
            for (int j = 0; j < 8; j++) {
                float2 p = *(const float2*)(&acc2[i2][j]);
                r[j] = half ? p.y : p.x;
            }
            if (ch >= 64 && ch < 96) {
                float bias = d_bcat[ch];
#pragma unroll
                for (int q = 0; q < 8; q += 4) {
                    int nf = n0 + tx * 8 + q;
                    int bb = nf / HW_;
                    int hw = nf - bb * HW_;
                    float4 v = make_float4(r[q] + bias, r[q + 1] + bias,
                                           r[q + 2] + bias, r[q + 3] + bias);
                    *(float4*)(d_theta + ((size_t)(bb * CI_ + (ch - 64))) * HW_ + hw) = v;
                }
            } else {
                unsigned* arr = (ch < 64) ? d_gx_u : d_phix_u;
                int pc = (ch < 64) ? ch : (ch - 96);
                int pst = (ch < 64) ? CG_ : CI_;
#pragma unroll
                for (int p = 0; p < 4; p++) {
                    float v = fmaxf(r[2 * p], r[2 * p + 1]);
                    int nf = n0 + tx * 8 + 2 * p;
                    int bb = nf / HW_;
                    int hw = nf - bb * HW_;
                    int h = hw / Wim_, w = hw - h * Wim_;
                    int pi = (h >> 1) * WP_ + (w >> 1);
                    atomicMax(arr + (bb * pst + pc) * NP_ + pi, enc_key(v));
                }
            }
        }
    }
}

// ---------------- S partials: 14 chunks of 56 positions (R14-kept) ----------------
__global__ void __launch_bounds__(256) k_S_part() {
    const int b = blockIdx.x;
    const int ch = blockIdx.y;
    const int m0 = ch * CHW_;
    __shared__ float phs[CI_][60];
    __shared__ float gs[CG_][60];
    float acc[8];
#pragma unroll
    for (int r = 0; r < 8; r++) acc[r] = 0.f;
    const int tid = threadIdx.x;
    const int ii = tid >> 3;
    const int cg_lane = tid & 7;

    for (int i = tid; i < CI_ * CHW_; i += 256) {
        int r = i / CHW_, mm = i % CHW_;
        unsigned u = d_phix_u[(b * CI_ + r) * NP_ + m0 + mm];
        phs[r][mm] = dec_key(u) + d_bcat[96 + r];
    }
    for (int i = tid; i < CG_ * CHW_; i += 256) {
        int r = i / CHW_, mm = i % CHW_;
        unsigned u = d_gx_u[(b * CG_ + r) * NP_ + m0 + mm];
        gs[r][mm] = dec_key(u) + d_bcat[r];
    }
    __syncthreads();
    for (int mm4 = 0; mm4 < CHW_; mm4 += 4) {
        float4 pv = *(const float4*)(&phs[ii][mm4]);
#pragma unroll
        for (int j = 0; j < 8; j++) {
            float4 gv = *(const float4*)(&gs[cg_lane + 8 * j][mm4]);
            acc[j] = fmaf(pv.x, gv.x, acc[j]);
            acc[j] = fmaf(pv.y, gv.y, acc[j]);
            acc[j] = fmaf(pv.z, gv.z, acc[j]);
            acc[j] = fmaf(pv.w, gv.w, acc[j]);
        }
    }
#pragma unroll
    for (int j = 0; j < 8; j++)
        d_Sp[((b * NCHK_ + ch) * CI_ + ii) * CG_ + cg_lane + 8 * j] = acc[j];
}

// ---------------- y = S^T @ theta, cg HALF per block (R13-proven) + fused BN2 partials ----------------
__global__ void __launch_bounds__(256) k_y() {
    const int b = blockIdx.y;
    const int z = blockIdx.z;               // half: channels [32z, 32z+32)
    const int tid = threadIdx.x;
    const int hw = blockIdx.x * 256 + tid;
    const bool valid = hw < HW_;

    __shared__ float Sh[CI_][32];
    __shared__ float sbuf[256][33];
    __shared__ float psS[8][32], psQ[8][32];

    for (int idx = tid; idx < CI_ * 32; idx += 256) {
        int i = idx >> 5, cl = idx & 31;
        float s = 0.f;
#pragma unroll
        for (int ch = 0; ch < NCHK_; ch++)
            s += d_Sp[((b * NCHK_ + ch) * CI_ + i) * CG_ + 32 * z + cl];
        Sh[i][cl] = s * (1.f / (float)NP_);
    }
    __syncthreads();

    u64 acc2[16];
#pragma unroll
    for (int c2 = 0; c2 < 16; c2++) acc2[c2] = 0ull;

    if (valid) {
#pragma unroll 4
        for (int i = 0; i < CI_; i++) {
            float t = d_theta[((size_t)(b * CI_ + i)) * HW_ + hw];
            u64 td; DUP2(td, t);
            const u64* row = (const u64*)(&Sh[i][0]);
#pragma unroll
            for (int c2 = 0; c2 < 16; c2++)
                FMA2(acc2[c2], td, row[c2]);
        }
    }

#pragma unroll
    for (int c2 = 0; c2 < 16; c2++) {
        float2 p = *(const float2*)(&acc2[c2]);
        if (valid) {
            d_y[((size_t)(b * CG_ + 32 * z + 2 * c2)) * HW_ + hw] = p.x;
            d_y[((size_t)(b * CG_ + 32 * z + 2 * c2 + 1)) * HW_ + hw] = p.y;
        }
        sbuf[tid][2 * c2] = valid ? p.x : 0.f;
        sbuf[tid][2 * c2 + 1] = valid ? p.y : 0.f;
    }
    __syncthreads();

    {
        int cl = tid & 31, seg = tid >> 5;
        float s = 0.f, q = 0.f;
#pragma unroll
        for (int r = 0; r < 32; r++) {
            float v = sbuf[seg * 32 + r][cl];
            s += v;
            q += v * v;
        }
        psS[seg][cl] = s;
        psQ[seg][cl] = q;
    }
    __syncthreads();
    if (tid < 32) {
        float S = 0.f, Q = 0.f;
#pragma unroll
        for (int seg = 0; seg < 8; seg++) { S += psS[seg][tid]; Q += psQ[seg][tid]; }
        int blk = blockIdx.x + HWB_ * b;
        d_ps2[(32 * z + tid) * NBLK2_ + blk] = S;
        d_pq2[(32 * z + tid) * NBLK2_ + blk] = Q;
    }
}

// ---------------- BN2 finalize ----------------
__global__ void __launch_bounds__(256) k_bn2_final(const float* __restrict__ gamma2,
                                                   const float* __restrict__ beta2) {
    const int tid = threadIdx.x;
    const int ch = tid & 63, qr = tid >> 6;
    float s = 0.f, q = 0.f;
    for (int p = qr * 52; p < (qr + 1) * 52; p++) {
        s += d_ps2[ch * NBLK2_ + p];
        q += d_pq2[ch * NBLK2_ + p];
    }
    __shared__ float ssm[4][64], sqm[4][64];
    ssm[qr][ch] = s;
    sqm[qr][ch] = q;
    __syncthreads();
    if (tid < 64) {
        float S = ssm[0][tid] + ssm[1][tid] + ssm[2][tid] + ssm[3][tid];
        float Q = sqm[0][tid] + sqm[1][tid] + sqm[2][tid] + sqm[3][tid];
        const float invN = 1.f / (float)(B_ * HW_);
        float mean = S * invN;
        float var = Q * invN - mean * mean;
        float inv = rsqrtf(var + 1e-5f);
        float g = gamma2[tid];
        d_a2[tid] = g * inv;
        d_b2[tid] = beta2[tid] - mean * g * inv;
    }
}

// ---------------- final GEMM (R13-proven): single K-pass, conflict-free ----------------
__global__ void __launch_bounds__(256) k_final(const float* __restrict__ bz,
                                               const float* __restrict__ x,
                                               float* __restrict__ out) {
    extern __shared__ float smemf[];
    float* As = smemf;
    float* Bs = smemf + 64 * 128;
    __shared__ float sa2[CG_], sb2[CG_];

    const int b  = blockIdx.z;
    const int m0 = blockIdx.y * 128;
    const int n0 = blockIdx.x * 128;
    const int tid = threadIdx.x;
    const int tx = tid & 15, ty = tid >> 4;

    if (tid < CG_) { sa2[tid] = d_a2[tid]; sb2[tid] = d_b2[tid]; }
    __syncthreads();

#pragma unroll
    for (int i = 0; i < 8; i++) {
        int idx = tid + i * 256;
        int k = idx >> 5;
        int m4 = (idx & 31) << 2;
        float4 v = *(const float4*)(d_wzT + k * C_ + m0 + m4);
        *(float4*)(&As[k * 128 + m4]) = v;
    }
#pragma unroll
    for (int i = 0; i < 8; i++) {
        int idx = tid + i * 256;
        int k = idx >> 5;
        int n4 = (idx & 31) << 2;
        int hw = n0 + n4;
        float4 v = make_float4(0.f, 0.f, 0.f, 0.f);
        if (hw < HW_)
            v = *(const float4*)(d_y + ((size_t)(b * CG_ + k)) * HW_ + hw);
        float a = sa2[k], bb = sb2[k];
        v.x = fmaxf(fmaf(a, v.x, bb), 0.f);
        v.y = fmaxf(fmaf(a, v.y, bb), 0.f);
        v.z = fmaxf(fmaf(a, v.z, bb), 0.f);
        v.w = fmaxf(fmaf(a, v.w, bb), 0.f);
        *(float4*)(&Bs[k * 132 + SWZ(n4)]) = v;
    }
    __syncthreads();

    const int oB1 = SWZ(tx * 8), oB2 = SWZ(tx * 8 + 4);
    u64 acc2[4][8];
#pragma unroll
    for (int i = 0; i < 4; i++)
#pragma unroll
        for (int j = 0; j < 8; j++) acc2[i][j] = 0ull;

#pragma unroll 4
    for (int k = 0; k < 64; k++) {
        ulonglong2 pa0 = *(const ulonglong2*)(&As[k * 128 + ty * 8]);
        ulonglong2 pa1 = *((const ulonglong2*)(&As[k * 128 + ty * 8]) + 1);
        u64 av2[4] = {pa0.x, pa0.y, pa1.x, pa1.y};
        float4 bq0 = *(const float4*)(&Bs[k * 132 + oB1]);
        float4 bq1 = *(const float4*)(&Bs[k * 132 + oB2]);
        u64 bd[8];
        DUP2(bd[0], bq0.x); DUP2(bd[1], bq0.y); DUP2(bd[2], bq0.z); DUP2(bd[3], bq0.w);
        DUP2(bd[4], bq1.x); DUP2(bd[5], bq1.y); DUP2(bd[6], bq1.z); DUP2(bd[7], bq1.w);
#pragma unroll
        for (int j = 0; j < 8; j++)
#pragma unroll
            for (int i2 = 0; i2 < 4; i2++)
                FMA2(acc2[i2][j], av2[i2], bd[j]);
    }

#pragma unroll
    for (int i2 = 0; i2 < 4; i2++) {
#pragma unroll
        for (int half = 0; half < 2; half++) {
            int m = m0 + ty * 8 + i2 * 2 + half;
            float bias = bz[m];
            float r[8];
#pragma unroll
            for (int j = 0; j < 8; j++) {
                float2 p = *(const float2*)(&acc2[i2][j]);
                r[j] = (half == 0 ? p.x : p.y) + bias;
            }
#pragma unroll
            for (int j4 = 0; j4 < 8; j4 += 4) {
                int n = n0 + tx * 8 + j4;
                if (n < HW_) {
                    size_t off = ((size_t)(b * C_ + m)) * HW_ + n;
                    float4 xi = *(const float4*)(x + off);
                    float4 v = make_float4(r[j4] + xi.x, r[j4 + 1] + xi.y,
                                           r[j4 + 2] + xi.z, r[j4 + 3] + xi.w);
                    *(float4*)(out + off) = v;
                }
            }
        }
    }
}

#define SMEM_FINAL ((64 * 128 + 64 * 132) * 4)

// ---------------- launch ----------------
extern "C" void kernel_launch(void* const* d_in, const int* in_sizes, int n_in,
                              void* d_out, int out_size) {
    const float* x   = (const float*)d_in[0];
    const float* g1  = (const float*)d_in[1];
    const float* be1 = (const float*)d_in[2];
    const float* w_g = (const float*)d_in[3];
    const float* b_g = (const float*)d_in[4];
    const float* w_t = (const float*)d_in[5];
    const float* b_t = (const float*)d_in[6];
    const float* w_p = (const float*)d_in[7];
    const float* b_p = (const float*)d_in[8];
    const float* g2  = (const float*)d_in[9];
    const float* be2 = (const float*)d_in[10];
    const float* wz  = (const float*)d_in[11];
    const float* bz  = (const float*)d_in[12];
    float* out = (float*)d_out;

    static int smem_set = 0;
    if (!smem_set) {
        cudaFuncSetAttribute(k_final, cudaFuncAttributeMaxDynamicSharedMemorySize, SMEM_FINAL);
        smem_set = 1;
    }

    k_front<<<dim3(C_, B_), 256>>>(x, w_g, b_g, w_t, b_t, w_p, b_p, wz);
    k_conv_cat<<<NTILE_, 256>>>(x, g1, be1);
    k_S_part<<<dim3(B_, NCHK_), 256>>>();
    k_y<<<dim3(HWB_, B_, 2), 256>>>();
    k_bn2_final<<<1, 256>>>(g2, be2);
    k_final<<<dim3(25, 2, B_), 256, SMEM_FINAL>>>(bz, x, out);
}